// round 8
// baseline (speedup 1.0000x reference)
#include <cuda_runtime.h>
#include <math.h>

#define BB   64
#define NN   4096
#define DD   1024
#define DIN  2048
#define DHID 4096
#define NOUT 1000

typedef unsigned long long ull;

#if defined(__CUDA_ARCH__) && (__CUDA_ARCH__ >= 900)
#define GRID_SYNC()  cudaGridDependencySynchronize()
#define GRID_TRIG()  cudaTriggerProgrammaticLaunchCompletion()
#else
#define GRID_SYNC()
#define GRID_TRIG()
#endif

// ---- scratch (device globals; no allocation allowed) ----
__device__ float g_xn[BB * DD];        // normalized encoder
__device__ float g_z[BB * NN];         // sparsemax input scores
__device__ int   g_nzidx[BB * NN];     // compacted support indices
__device__ float g_nzw[BB * NN];       // compacted weights
__device__ int   g_nnz[BB];
__device__ float g_memvec[BB * DD];    // weighted memory readout (atomic acc)
__device__ float g_h1[BB * DHID];      // hidden pre-activations (bias + atomic acc)

// ---------------------------------------------------------------------------
// PRE1: xn = enc / max(||enc||, 1e-6)    (64 blocks x 256) — launch #1
// ---------------------------------------------------------------------------
__global__ void pre1_norm(const float* __restrict__ enc) {
    int b = blockIdx.x;
    __shared__ float red[256];
    float ssq = 0.f;
    for (int i = threadIdx.x; i < DD; i += 256) {
        float v = enc[b * DD + i];
        ssq = fmaf(v, v, ssq);
    }
    red[threadIdx.x] = ssq;
    __syncthreads();
    for (int s = 128; s > 0; s >>= 1) {
        if (threadIdx.x < s) red[threadIdx.x] += red[threadIdx.x + s];
        __syncthreads();
    }
    float inv = 1.f / fmaxf(sqrtf(red[0]), 1e-6f);
    for (int i = threadIdx.x; i < DD; i += 256)
        g_xn[b * DD + i] = enc[b * DD + i] * inv;
}

// ---------------------------------------------------------------------------
// PRE2: h1 = b1 (bcast), memvec = 0, out = b2 (bcast) — launch #2
//       1530 blocks x 256
// ---------------------------------------------------------------------------
__global__ void pre2_init(const float* __restrict__ b1,
                          const float* __restrict__ b2,
                          float* __restrict__ out) {
    int bid = blockIdx.x;
    if (bid < 1024) {
        int i = bid * 256 + threadIdx.x;               // BB*DHID
        g_h1[i] = b1[i & (DHID - 1)];
    } else if (bid < 1280) {
        int i = (bid - 1024) * 256 + threadIdx.x;      // BB*DD
        g_memvec[i] = 0.f;
    } else {
        int i = (bid - 1280) * 256 + threadIdx.x;      // BB*NOUT
        if (i < BB * NOUT) out[i] = b2[i % NOUT];
    }
}

// ---------------------------------------------------------------------------
// K1: the 1.07 GB pass (AT DRAM ROOFLINE — do not touch). Launch #3.
// ---------------------------------------------------------------------------
__global__ void __launch_bounds__(256) k1_scores(const float* __restrict__ mem) {
    int warp = threadIdx.x >> 5, lane = threadIdx.x & 31;
    int rbase = blockIdx.x * 64 + warp * 8;
    int b = rbase >> 12;

    const float4* x4 = (const float4*)g_xn + (size_t)b * (DD / 4);
    float4 x[8];
#pragma unroll
    for (int i = 0; i < 8; i++) x[i] = x4[lane + i * 32];

    const float4* mrow = (const float4*)mem + (size_t)rbase * (DD / 4);

#pragma unroll
    for (int rr = 0; rr < 8; rr += 2) {
        const float4* A = mrow + rr * (DD / 4);
        const float4* C = A + (DD / 4);
        float4 a[8], c[8];
#pragma unroll
        for (int i = 0; i < 8; i++) {
            a[i] = __ldcs(&A[lane + i * 32]);
            c[i] = __ldcs(&C[lane + i * 32]);
        }
        float d0 = 0.f, s0 = 0.f, d1 = 0.f, s1 = 0.f;
#pragma unroll
        for (int i = 0; i < 8; i++) {
            float4 xv = x[i];
            d0 = fmaf(a[i].x, xv.x, fmaf(a[i].y, xv.y, fmaf(a[i].z, xv.z, fmaf(a[i].w, xv.w, d0))));
            s0 = fmaf(a[i].x, a[i].x, fmaf(a[i].y, a[i].y, fmaf(a[i].z, a[i].z, fmaf(a[i].w, a[i].w, s0))));
            d1 = fmaf(c[i].x, xv.x, fmaf(c[i].y, xv.y, fmaf(c[i].z, xv.z, fmaf(c[i].w, xv.w, d1))));
            s1 = fmaf(c[i].x, c[i].x, fmaf(c[i].y, c[i].y, fmaf(c[i].z, c[i].z, fmaf(c[i].w, c[i].w, s1))));
        }
#pragma unroll
        for (int o = 16; o; o >>= 1) {
            d0 += __shfl_xor_sync(0xFFFFFFFFu, d0, o);
            s0 += __shfl_xor_sync(0xFFFFFFFFu, s0, o);
            d1 += __shfl_xor_sync(0xFFFFFFFFu, d1, o);
            s1 += __shfl_xor_sync(0xFFFFFFFFu, s1, o);
        }
        if (lane == 0) {
            g_z[rbase + rr]     = d0 / fmaxf(sqrtf(s0), 1e-6f) - 1.0f;
            g_z[rbase + rr + 1] = d1 / fmaxf(sqrtf(s1), 1e-6f) - 1.0f;
        }
    }
}

// ---------------------------------------------------------------------------
// K2: sparsemax (Michelot). PDL secondary of k1: sync before reading z.
//     Launch #4 -> gets the ncu capture this round.
// ---------------------------------------------------------------------------
__global__ void k2_sparsemax() {
    GRID_SYNC();                               // wait k1's z
    int b = blockIdx.x, t = threadIdx.x;
    int lane = t & 31, w = t >> 5;             // 16 warps
    __shared__ float sS[16], sK[16];
    __shared__ float s_tau;
    __shared__ int cnt;

    float loc[8];
#pragma unroll
    for (int i = 0; i < 8; i++) loc[i] = g_z[b * NN + t + i * 512];

    float S = 0.f;
#pragma unroll
    for (int i = 0; i < 8; i++) S += loc[i];
#pragma unroll
    for (int o = 16; o; o >>= 1) S += __shfl_xor_sync(0xFFFFFFFFu, S, o);
    if (lane == 0) sS[w] = S;
    __syncthreads();
    if (w == 0) {
        float ss = (lane < 16) ? sS[lane] : 0.f;
#pragma unroll
        for (int o = 8; o; o >>= 1) ss += __shfl_xor_sync(0xFFFFFFFFu, ss, o);
        if (lane == 0) s_tau = (ss - 1.f) / (float)NN;
    }
    __syncthreads();
    float tau = s_tau;

    for (int it = 0; it < 48; it++) {
        float s = 0.f, k = 0.f;
#pragma unroll
        for (int i = 0; i < 8; i++) {
            float v = loc[i];
            if (v > tau) { s += v; k += 1.f; }
        }
#pragma unroll
        for (int o = 16; o; o >>= 1) {
            s += __shfl_xor_sync(0xFFFFFFFFu, s, o);
            k += __shfl_xor_sync(0xFFFFFFFFu, k, o);
        }
        if (lane == 0) { sS[w] = s; sK[w] = k; }
        __syncthreads();
        if (w == 0) {
            float ss = (lane < 16) ? sS[lane] : 0.f;
            float kk = (lane < 16) ? sK[lane] : 0.f;
#pragma unroll
            for (int o = 8; o; o >>= 1) {
                ss += __shfl_xor_sync(0xFFFFFFFFu, ss, o);
                kk += __shfl_xor_sync(0xFFFFFFFFu, kk, o);
            }
            if (lane == 0) s_tau = (ss - 1.f) / kk;
        }
        __syncthreads();
        float tn = s_tau;
        if (!(tn > tau)) break;
        tau = tn;
    }

    if (t == 0) cnt = 0;
    __syncthreads();
#pragma unroll
    for (int i = 0; i < 8; i++) {
        float wv = loc[i] - tau;
        if (wv > 0.f) {
            int p = atomicAdd(&cnt, 1);
            g_nzidx[b * NN + p] = t + i * 512;
            g_nzw[b * NN + p] = wv;
        }
    }
    __syncthreads();
    if (t == 0) g_nnz[b] = cnt;
}

// ---------------------------------------------------------------------------
// K3: sparse weighted sum. PDL secondary of k2. Triggers IMMEDIATELY so k4's
//     enc-half blocks launch and run concurrently with k3.
// ---------------------------------------------------------------------------
__global__ void __launch_bounds__(256) k3_weighted_sum(const float* __restrict__ mem) {
    GRID_TRIG();                               // let k4 start now
    GRID_SYNC();                               // wait k2's nnz/idx/w
    int b = blockIdx.x, s = blockIdx.y, t = threadIdx.x;
    int nnz = g_nnz[b];

    const float4* base = (const float4*)mem + (size_t)b * NN * (DD / 4);
    const int*   idxp = &g_nzidx[b * NN];
    const float* wp   = &g_nzw[b * NN];

    float4 acc = make_float4(0.f, 0.f, 0.f, 0.f);
    int i = s * 2;
    bool any = (i < nnz);
    for (; i + 2 <= nnz; i += 32) {
        int   j0 = idxp[i],   j1 = idxp[i + 1];
        float w0 = wp[i],     w1 = wp[i + 1];
        float4 m0 = __ldcs(&base[(size_t)j0 * (DD / 4) + t]);
        float4 m1 = __ldcs(&base[(size_t)j1 * (DD / 4) + t]);
        acc.x = fmaf(w0, m0.x, fmaf(w1, m1.x, acc.x));
        acc.y = fmaf(w0, m0.y, fmaf(w1, m1.y, acc.y));
        acc.z = fmaf(w0, m0.z, fmaf(w1, m1.z, acc.z));
        acc.w = fmaf(w0, m0.w, fmaf(w1, m1.w, acc.w));
    }
    if (i < nnz) {
        int j = idxp[i];
        float wv = wp[i];
        float4 m = __ldcs(&base[(size_t)j * (DD / 4) + t]);
        acc.x = fmaf(wv, m.x, acc.x);
        acc.y = fmaf(wv, m.y, acc.y);
        acc.z = fmaf(wv, m.z, acc.z);
        acc.w = fmaf(wv, m.w, acc.w);
    }
    if (!any) return;
    float* dst = &g_memvec[b * DD + t * 4];
    atomicAdd(dst + 0, acc.x);
    atomicAdd(dst + 1, acc.y);
    atomicAdd(dst + 2, acc.z);
    atomicAdd(dst + 3, acc.w);
}

// ---------------------------------------------------------------------------
// K4: h1 += [enc, memvec] @ W1^T. grid (64, 4).
//     y<2: enc half — NO dependency sync; runs concurrently with k3.
//     y>=2: prefetch W1 tile to L2, then sync on memvec, then compute.
//     Triggers immediately so k5 can prefetch W2 during k4.
// ---------------------------------------------------------------------------
__global__ void k4_fc1(const float* __restrict__ enc,
                       const float* __restrict__ W1) {
    GRID_TRIG();                               // let k5 start prefetching
    __shared__ float2 sw2[64][33];
    __shared__ float2 sh2[32][33];
    int t = threadIdx.x;
    int obase = blockIdx.x * 64;
    int y = blockIdx.y;
    bool encHalf = (y < 2);
    int koff = (y & 1) * 512;                  // within the 1024-wide half
    int ol = t & 31;
    int bg = t >> 5;

    const float* Wb = W1 + (size_t)obase * DIN + (encHalf ? 0 : DD);
    const float* src = encHalf ? enc : (const float*)g_memvec;

    if (!encHalf) {
        // prefetch this block's W1 tile (64 rows x 512 cols) into L2 pre-sync
        for (int l = t; l < 1024; l += 256) {
            int row = l >> 4, seg = l & 15;
            const char* p = (const char*)(Wb + (size_t)row * DIN + koff) + seg * 128;
            asm volatile("prefetch.global.L2 [%0];" :: "l"(p));
        }
        GRID_SYNC();                           // wait k3's memvec
    }

    ull accA[4] = {0ull, 0ull, 0ull, 0ull};
    ull accB[4] = {0ull, 0ull, 0ull, 0ull};

    for (int kc = koff; kc < koff + 512; kc += 32) {
#pragma unroll
        for (int i = 0; i < 8; i++) {          // 64x32 h tile
            int e = t + i * 256;
            int row = e >> 5, col = e & 31;
            ((float*)&sh2[row >> 1][col])[row & 1] = src[row * DD + kc + col];
        }
#pragma unroll
        for (int i = 0; i < 8; i++) {          // 64x32 W tile, splat
            int e = t + i * 256;
            int row = e >> 5, col = e & 31;
            float wv = Wb[(size_t)row * DIN + kc + col];
            sw2[row][col] = make_float2(wv, wv);
        }
        __syncthreads();
#pragma unroll
        for (int kk = 0; kk < 32; kk++) {
            ull wa = *(const ull*)&sw2[ol][kk];
            ull wb = *(const ull*)&sw2[ol + 32][kk];
#pragma unroll
            for (int j = 0; j < 4; j++) {
                ull h2 = *(const ull*)&sh2[bg * 4 + j][kk];
                asm("fma.rn.f32x2 %0, %1, %2, %0;" : "+l"(accA[j]) : "l"(h2), "l"(wa));
                asm("fma.rn.f32x2 %0, %1, %2, %0;" : "+l"(accB[j]) : "l"(h2), "l"(wb));
            }
        }
        __syncthreads();
    }
    int o0 = obase + ol, o1 = obase + 32 + ol;
#pragma unroll
    for (int j = 0; j < 4; j++) {
        float lo, hi;
        int p = bg * 8 + j * 2;
        asm("mov.b64 {%0, %1}, %2;" : "=f"(lo), "=f"(hi) : "l"(accA[j]));
        atomicAdd(&g_h1[(size_t)p * DHID + o0], lo);
        atomicAdd(&g_h1[(size_t)(p + 1) * DHID + o0], hi);
        asm("mov.b64 {%0, %1}, %2;" : "=f"(lo), "=f"(hi) : "l"(accB[j]));
        atomicAdd(&g_h1[(size_t)p * DHID + o1], lo);
        atomicAdd(&g_h1[(size_t)(p + 1) * DHID + o1], hi);
    }
}

// ---------------------------------------------------------------------------
// K5: out += relu(h1) @ W2^T. grid (16, 8). PDL secondary of k4: prefetch W2
//     tile to L2 BEFORE syncing on h1.
// ---------------------------------------------------------------------------
__global__ void k5_fc2(const float* __restrict__ W2, float* __restrict__ out) {
    __shared__ float2 sw2[64][33];
    __shared__ float2 sh2[32][33];
    int t = threadIdx.x;
    int obase = blockIdx.x * 64;
    int kbeg = blockIdx.y * (DHID / 8);
    int ol = t & 31;
    int bg = t >> 5;

    // prefetch this block's W2 tile (rows < NOUT only) into L2 pre-sync
    for (int l = t; l < 1024; l += 256) {
        int row = l >> 4, seg = l & 15;
        int o = obase + row;
        if (o < NOUT) {
            const char* p = (const char*)(W2 + (size_t)o * DHID + kbeg) + seg * 128;
            asm volatile("prefetch.global.L2 [%0];" :: "l"(p));
        }
    }
    GRID_SYNC();                               // wait k4's h1

    ull accA[4] = {0ull, 0ull, 0ull, 0ull};
    ull accB[4] = {0ull, 0ull, 0ull, 0ull};

    for (int kc = kbeg; kc < kbeg + DHID / 8; kc += 32) {
#pragma unroll
        for (int i = 0; i < 8; i++) {
            int e = t + i * 256;
            int row = e >> 5, col = e & 31;
            float v = fmaxf(g_h1[(size_t)row * DHID + kc + col], 0.f);  // relu
            ((float*)&sh2[row >> 1][col])[row & 1] = v;
        }
#pragma unroll
        for (int i = 0; i < 8; i++) {
            int e = t + i * 256;
            int row = e >> 5, col = e & 31;
            int o = obase + row;
            float wv = (o < NOUT) ? W2[(size_t)o * DHID + kc + col] : 0.f;
            sw2[row][col] = make_float2(wv, wv);
        }
        __syncthreads();
#pragma unroll
        for (int kk = 0; kk < 32; kk++) {
            ull wa = *(const ull*)&sw2[ol][kk];
            ull wb = *(const ull*)&sw2[ol + 32][kk];
#pragma unroll
            for (int j = 0; j < 4; j++) {
                ull h2 = *(const ull*)&sh2[bg * 4 + j][kk];
                asm("fma.rn.f32x2 %0, %1, %2, %0;" : "+l"(accA[j]) : "l"(h2), "l"(wa));
                asm("fma.rn.f32x2 %0, %1, %2, %0;" : "+l"(accB[j]) : "l"(h2), "l"(wb));
            }
        }
        __syncthreads();
    }
    int o0 = obase + ol, o1 = obase + 32 + ol;
#pragma unroll
    for (int j = 0; j < 4; j++) {
        float lo, hi;
        int p = bg * 8 + j * 2;
        if (o0 < NOUT) {
            asm("mov.b64 {%0, %1}, %2;" : "=f"(lo), "=f"(hi) : "l"(accA[j]));
            atomicAdd(&out[(size_t)p * NOUT + o0], lo);
            atomicAdd(&out[(size_t)(p + 1) * NOUT + o0], hi);
        }
        if (o1 < NOUT) {
            asm("mov.b64 {%0, %1}, %2;" : "=f"(lo), "=f"(hi) : "l"(accB[j]));
            atomicAdd(&out[(size_t)p * NOUT + o1], lo);
            atomicAdd(&out[(size_t)(p + 1) * NOUT + o1], hi);
        }
    }
}

// ---------------------------------------------------------------------------
extern "C" void kernel_launch(void* const* d_in, const int* in_sizes, int n_in,
                              void* d_out, int out_size) {
    const float* enc = (const float*)d_in[0];   // [64,1024]
    const float* mem = (const float*)d_in[1];   // [64,4096,1024]
    const float* W1  = (const float*)d_in[2];   // [4096,2048]
    const float* b1  = (const float*)d_in[3];   // [4096]
    const float* W2  = (const float*)d_in[4];   // [1000,4096]
    const float* b2  = (const float*)d_in[5];   // [1000]
    float* out = (float*)d_out;                 // [64,1000]

    pre1_norm<<<BB, 256>>>(enc);                          // launch 1
    pre2_init<<<1530, 256>>>(b1, b2, out);                // launch 2
    k1_scores<<<(BB * NN) / 64, 256>>>(mem);              // launch 3

    cudaLaunchAttribute at[1];
    at[0].id = cudaLaunchAttributeProgrammaticStreamSerialization;
    at[0].val.programmaticStreamSerializationAllowed = 1;
    cudaLaunchConfig_t cfg = {};
    cfg.attrs = at;
    cfg.numAttrs = 1;
    cfg.stream = 0;                                       // legacy (capture) stream

    cfg.gridDim = dim3(BB); cfg.blockDim = dim3(512);
    cudaLaunchKernelEx(&cfg, k2_sparsemax);               // launch 4 -> profiled

    cfg.gridDim = dim3(BB, 16); cfg.blockDim = dim3(256);
    cudaLaunchKernelEx(&cfg, k3_weighted_sum, mem);       // launch 5

    cfg.gridDim = dim3(DHID / 64, 4); cfg.blockDim = dim3(256);
    cudaLaunchKernelEx(&cfg, k4_fc1, enc, W1);            // launch 6

    cfg.gridDim = dim3(16, 8); cfg.blockDim = dim3(256);
    cudaLaunchKernelEx(&cfg, k5_fc2, W2, out);            // launch 7
}